// round 1
// baseline (speedup 1.0000x reference)
#include <cuda_runtime.h>

#define NV   8192
#define DIM  128
#define MAX_NNZ 80
#define K2_ROWS 16

// ---- scratch (no allocations allowed) ----
__device__ int   g_cols[NV * MAX_NNZ];   // per-row nonzero column indices
__device__ int   g_cnt [NV];             // per-row nnz count (excl. identity)
__device__ float g_dinv[NV];             // (deg+1)^-0.5
__device__ float g_G   [NV * DIM];       // D^-1/2 * (H @ W^T + b)
__device__ float g_WT  [DIM * DIM];      // W transposed: [k][o]

// ---------------------------------------------------------------------------
// K1: one block per row of A. Streams 268 MB, extracts nnz pattern + degree.
// ---------------------------------------------------------------------------
__global__ void k1_scan(const float* __restrict__ A) {
    __shared__ int s_cnt;
    const int row = blockIdx.x;
    if (threadIdx.x == 0) s_cnt = 0;
    __syncthreads();

    const float4* rp = reinterpret_cast<const float4*>(A + (size_t)row * NV);
    int* mycols = g_cols + row * MAX_NNZ;

#pragma unroll
    for (int it = 0; it < 8; ++it) {
        const int idx = threadIdx.x + it * 256;   // 2048 float4 per row
        const float4 v = rp[idx];
        const int base = idx * 4;
        if (v.x != 0.0f) { int p = atomicAdd(&s_cnt, 1); if (p < MAX_NNZ) mycols[p] = base + 0; }
        if (v.y != 0.0f) { int p = atomicAdd(&s_cnt, 1); if (p < MAX_NNZ) mycols[p] = base + 1; }
        if (v.z != 0.0f) { int p = atomicAdd(&s_cnt, 1); if (p < MAX_NNZ) mycols[p] = base + 2; }
        if (v.w != 0.0f) { int p = atomicAdd(&s_cnt, 1); if (p < MAX_NNZ) mycols[p] = base + 3; }
    }
    __syncthreads();
    if (threadIdx.x == 0) {
        const int c = s_cnt;
        g_cnt[row]  = c < MAX_NNZ ? c : MAX_NNZ;
        g_dinv[row] = rsqrtf((float)c + 1.0f);    // deg = nnz + 1 (identity)
    }
}

// ---------------------------------------------------------------------------
// K0: transpose W [o][k] -> g_WT [k][o] so K2 reads coalesced along o.
// ---------------------------------------------------------------------------
__global__ void k0_transpose(const float* __restrict__ W) {
    const int i = blockIdx.x * blockDim.x + threadIdx.x;   // 16384
    const int o = i >> 7, k = i & 127;
    g_WT[k * DIM + o] = W[i];
}

// ---------------------------------------------------------------------------
// K2: G[r][o] = dinv[r] * (sum_k H[r][k]*W[o][k] + b[o]).
// 256 threads: o = tid&127, each thread register-blocks 8 rows.
// Hs stored k-major (Hs[k][r]) so one LDS.128 feeds 4 FMAs.
// ---------------------------------------------------------------------------
__global__ void k2_linear(const float* __restrict__ H, const float* __restrict__ b) {
    __shared__ float Hs[DIM * K2_ROWS];   // [k*16 + r]
    const int t = threadIdx.x;            // 256
    const int row0 = blockIdx.x * K2_ROWS;

    for (int i = t; i < K2_ROWS * DIM; i += 256) {
        const int r = i >> 7, k = i & 127;
        Hs[k * K2_ROWS + r] = H[(size_t)(row0 + r) * DIM + k];
    }
    __syncthreads();

    const int o  = t & 127;
    const int rh = (t >> 7) * 8;          // 0 or 8
    const float bo = b[o];

    float acc[8];
#pragma unroll
    for (int i = 0; i < 8; ++i) acc[i] = bo;

#pragma unroll 4
    for (int k = 0; k < DIM; ++k) {
        const float w = g_WT[k * DIM + o];
        const float4 h0 = *reinterpret_cast<const float4*>(&Hs[k * K2_ROWS + rh]);
        const float4 h1 = *reinterpret_cast<const float4*>(&Hs[k * K2_ROWS + rh + 4]);
        acc[0] += h0.x * w; acc[1] += h0.y * w; acc[2] += h0.z * w; acc[3] += h0.w * w;
        acc[4] += h1.x * w; acc[5] += h1.y * w; acc[6] += h1.z * w; acc[7] += h1.w * w;
    }

#pragma unroll
    for (int i = 0; i < 8; ++i) {
        const int r = row0 + rh + i;
        g_G[(size_t)r * DIM + o] = g_dinv[r] * acc[i];
    }
}

// ---------------------------------------------------------------------------
// K3: one warp per output row. acc starts at G[i] (identity), gathers
// neighbor rows of G (L2-resident), scales by dinv[i], relu, store.
// ---------------------------------------------------------------------------
__global__ void k3_spmm(float* __restrict__ out) {
    const int gw   = (blockIdx.x * blockDim.x + threadIdx.x) >> 5;
    const int lane = threadIdx.x & 31;
    if (gw >= NV) return;

    const float4* G4 = reinterpret_cast<const float4*>(g_G);
    float4 a0 = G4[(size_t)gw * 32 + lane];     // identity term
    float4 a1 = make_float4(0.f, 0.f, 0.f, 0.f);

    const int  cnt  = g_cnt[gw];
    const int* cols = g_cols + gw * MAX_NNZ;

    int k = 0;
    for (; k + 2 <= cnt; k += 2) {
        const int j0 = cols[k], j1 = cols[k + 1];
        const float4 v0 = G4[(size_t)j0 * 32 + lane];
        const float4 v1 = G4[(size_t)j1 * 32 + lane];
        a0.x += v0.x; a0.y += v0.y; a0.z += v0.z; a0.w += v0.w;
        a1.x += v1.x; a1.y += v1.y; a1.z += v1.z; a1.w += v1.w;
    }
    if (k < cnt) {
        const float4 v0 = G4[(size_t)cols[k] * 32 + lane];
        a0.x += v0.x; a0.y += v0.y; a0.z += v0.z; a0.w += v0.w;
    }

    const float di = g_dinv[gw];
    float4 r;
    r.x = fmaxf((a0.x + a1.x) * di, 0.0f);
    r.y = fmaxf((a0.y + a1.y) * di, 0.0f);
    r.z = fmaxf((a0.z + a1.z) * di, 0.0f);
    r.w = fmaxf((a0.w + a1.w) * di, 0.0f);
    reinterpret_cast<float4*>(out)[(size_t)gw * 32 + lane] = r;
}

// ---------------------------------------------------------------------------
extern "C" void kernel_launch(void* const* d_in, const int* in_sizes, int n_in,
                              void* d_out, int out_size) {
    const float* H = (const float*)d_in[0];   // [8192,128]
    const float* A = (const float*)d_in[1];   // [8192,8192]
    const float* W = (const float*)d_in[2];   // [128,128]
    const float* b = (const float*)d_in[3];   // [128]
    float* out = (float*)d_out;

    k1_scan<<<NV, 256>>>(A);
    k0_transpose<<<(DIM * DIM) / 256, 256>>>(W);
    k2_linear<<<NV / K2_ROWS, 256>>>(H, b);
    k3_spmm<<<NV / 8, 256>>>(out);
}

// round 2
// speedup vs baseline: 1.0058x; 1.0058x over previous
#include <cuda_runtime.h>

#define NV   8192
#define DIM  128
#define MAX_NNZ 80
#define K2_ROWS 16
#define NLIN (NV / K2_ROWS)   // 512 linear blocks, scheduled FIRST for overlap

// ---- scratch (no allocations allowed) ----
__device__ int   g_cols[NV * MAX_NNZ];   // per-row nonzero column indices
__device__ int   g_cnt [NV];             // per-row nnz count (excl. identity)
__device__ float g_dinv[NV];             // (deg+1)^-0.5
__device__ float g_G   [NV * DIM];       // UNNORMALIZED  H @ W^T + b
__device__ float g_WT  [DIM * DIM];      // W transposed: [k][o]

// ---------------------------------------------------------------------------
// K0: transpose W [o][k] -> g_WT [k][o] so the linear blocks read coalesced.
// ---------------------------------------------------------------------------
__global__ void k0_transpose(const float* __restrict__ W) {
    const int i = blockIdx.x * blockDim.x + threadIdx.x;   // 16384
    const int o = i >> 7, k = i & 127;
    g_WT[k * DIM + o] = W[i];
}

// ---------------------------------------------------------------------------
// Fused kernel:
//   blocks [0, NLIN)      : linear  G[r] = H[r] @ W^T + b      (compute-bound)
//   blocks [NLIN, NLIN+NV): scan one row of A                  (DRAM-bound)
// The 512 compute blocks hide entirely under the 268 MB A-stream.
// ---------------------------------------------------------------------------
__global__ void k_fused(const float* __restrict__ A,
                        const float* __restrict__ H,
                        const float* __restrict__ b) {
    __shared__ float Hs[DIM * K2_ROWS];   // linear branch: [k*16 + r]  (8 KB)
    __shared__ int   s_cnt;               // scan branch

    if (blockIdx.x < NLIN) {
        // ---------------- linear branch ----------------
        const int t = threadIdx.x;            // 256
        const int row0 = blockIdx.x * K2_ROWS;

        for (int i = t; i < K2_ROWS * DIM; i += 256) {
            const int r = i >> 7, k = i & 127;
            Hs[k * K2_ROWS + r] = H[(size_t)(row0 + r) * DIM + k];
        }
        __syncthreads();

        const int o  = t & 127;
        const int rh = (t >> 7) * 8;          // 0 or 8
        const float bo = __ldg(&b[o]);

        float acc[8];
#pragma unroll
        for (int i = 0; i < 8; ++i) acc[i] = bo;

#pragma unroll 4
        for (int k = 0; k < DIM; ++k) {
            const float w = g_WT[k * DIM + o];
            const float4 h0 = *reinterpret_cast<const float4*>(&Hs[k * K2_ROWS + rh]);
            const float4 h1 = *reinterpret_cast<const float4*>(&Hs[k * K2_ROWS + rh + 4]);
            acc[0] += h0.x * w; acc[1] += h0.y * w; acc[2] += h0.z * w; acc[3] += h0.w * w;
            acc[4] += h1.x * w; acc[5] += h1.y * w; acc[6] += h1.z * w; acc[7] += h1.w * w;
        }

#pragma unroll
        for (int i = 0; i < 8; ++i) {
            const int r = row0 + rh + i;
            g_G[(size_t)r * DIM + o] = acc[i];          // no dinv here
        }
    } else {
        // ---------------- scan branch ----------------
        const int row = blockIdx.x - NLIN;
        if (threadIdx.x == 0) s_cnt = 0;
        __syncthreads();

        const float4* rp = reinterpret_cast<const float4*>(A + (size_t)row * NV);
        int* mycols = g_cols + row * MAX_NNZ;

#pragma unroll
        for (int it = 0; it < 8; ++it) {
            const int idx = threadIdx.x + it * 256;     // 2048 float4 per row
            const float4 v = __ldcs(rp + idx);          // evict-first stream
            const int base = idx * 4;
            if (v.x != 0.0f) { int p = atomicAdd(&s_cnt, 1); if (p < MAX_NNZ) mycols[p] = base + 0; }
            if (v.y != 0.0f) { int p = atomicAdd(&s_cnt, 1); if (p < MAX_NNZ) mycols[p] = base + 1; }
            if (v.z != 0.0f) { int p = atomicAdd(&s_cnt, 1); if (p < MAX_NNZ) mycols[p] = base + 2; }
            if (v.w != 0.0f) { int p = atomicAdd(&s_cnt, 1); if (p < MAX_NNZ) mycols[p] = base + 3; }
        }
        __syncthreads();
        if (threadIdx.x == 0) {
            const int c = s_cnt;
            g_cnt[row]  = c < MAX_NNZ ? c : MAX_NNZ;
            g_dinv[row] = rsqrtf((float)c + 1.0f);      // deg = nnz + 1 (identity)
        }
    }
}

// ---------------------------------------------------------------------------
// K3: one warp per output row.
//   out[i] = relu( dinv[i] * ( dinv[i]*G[i] + sum_j dinv[j]*G[j] ) )
// 4-way unrolled gather for MLP=4 (L2-latency-bound).
// ---------------------------------------------------------------------------
__global__ void k3_spmm(float* __restrict__ out) {
    const int gw   = (blockIdx.x * blockDim.x + threadIdx.x) >> 5;
    const int lane = threadIdx.x & 31;
    if (gw >= NV) return;

    const float4* G4 = reinterpret_cast<const float4*>(g_G);
    const float di = g_dinv[gw];

    const float4 gi = __ldg(&G4[(size_t)gw * 32 + lane]);
    float4 a0, a1, a2, a3;
    a0.x = di * gi.x; a0.y = di * gi.y; a0.z = di * gi.z; a0.w = di * gi.w;
    a1 = make_float4(0.f, 0.f, 0.f, 0.f);
    a2 = make_float4(0.f, 0.f, 0.f, 0.f);
    a3 = make_float4(0.f, 0.f, 0.f, 0.f);

    const int  cnt  = g_cnt[gw];
    const int* cols = g_cols + gw * MAX_NNZ;

    int k = 0;
    for (; k + 4 <= cnt; k += 4) {
        const int j0 = cols[k], j1 = cols[k + 1], j2 = cols[k + 2], j3 = cols[k + 3];
        const float d0 = __ldg(&g_dinv[j0]);
        const float d1 = __ldg(&g_dinv[j1]);
        const float d2 = __ldg(&g_dinv[j2]);
        const float d3 = __ldg(&g_dinv[j3]);
        const float4 v0 = __ldg(&G4[(size_t)j0 * 32 + lane]);
        const float4 v1 = __ldg(&G4[(size_t)j1 * 32 + lane]);
        const float4 v2 = __ldg(&G4[(size_t)j2 * 32 + lane]);
        const float4 v3 = __ldg(&G4[(size_t)j3 * 32 + lane]);
        a0.x += d0 * v0.x; a0.y += d0 * v0.y; a0.z += d0 * v0.z; a0.w += d0 * v0.w;
        a1.x += d1 * v1.x; a1.y += d1 * v1.y; a1.z += d1 * v1.z; a1.w += d1 * v1.w;
        a2.x += d2 * v2.x; a2.y += d2 * v2.y; a2.z += d2 * v2.z; a2.w += d2 * v2.w;
        a3.x += d3 * v3.x; a3.y += d3 * v3.y; a3.z += d3 * v3.z; a3.w += d3 * v3.w;
    }
    for (; k < cnt; ++k) {
        const int j0 = cols[k];
        const float d0 = __ldg(&g_dinv[j0]);
        const float4 v0 = __ldg(&G4[(size_t)j0 * 32 + lane]);
        a0.x += d0 * v0.x; a0.y += d0 * v0.y; a0.z += d0 * v0.z; a0.w += d0 * v0.w;
    }

    float4 r;
    r.x = fmaxf((a0.x + a1.x + a2.x + a3.x) * di, 0.0f);
    r.y = fmaxf((a0.y + a1.y + a2.y + a3.y) * di, 0.0f);
    r.z = fmaxf((a0.z + a1.z + a2.z + a3.z) * di, 0.0f);
    r.w = fmaxf((a0.w + a1.w + a2.w + a3.w) * di, 0.0f);
    reinterpret_cast<float4*>(out)[(size_t)gw * 32 + lane] = r;
}

// ---------------------------------------------------------------------------
extern "C" void kernel_launch(void* const* d_in, const int* in_sizes, int n_in,
                              void* d_out, int out_size) {
    const float* H = (const float*)d_in[0];   // [8192,128]
    const float* A = (const float*)d_in[1];   // [8192,8192]
    const float* W = (const float*)d_in[2];   // [128,128]
    const float* b = (const float*)d_in[3];   // [128]
    float* out = (float*)d_out;

    k0_transpose<<<(DIM * DIM) / 256, 256>>>(W);
    k_fused<<<NLIN + NV, 256>>>(A, H, b);
    k3_spmm<<<NV / 8, 256>>>(out);
}